// round 12
// baseline (speedup 1.0000x reference)
#include <cuda_runtime.h>
#include <cstdint>
#include <cstddef>

#define VERY_NEG -1e30f
#define B_   128
#define S_   256
#define H_   256
#define C_   20000
#define A_   8
#define BS_  (B_*S_)      // 32768
#define CA_  (C_*A_)      // 160000

// ================= scratch =================
__device__ float g_dict[(C_+1)*H_];
__device__ float g_xv[BS_*H_];
__device__ float g_xd[BS_*H_];
__device__ float g_t1[BS_*H_];
__device__ float g_qkv[BS_*768];
__device__ float g_ctx[BS_*H_];
__device__ float g_ff[BS_*4*H_];
__device__ float g_wT[1703936 + 256];   // tf32-RNA pre-rounded transposed weights
__device__ float g_scores[CA_];

// ================= PTX helpers =================
__device__ __forceinline__ uint32_t smem_u32(const void* p) {
    uint32_t a;
    asm("{ .reg .u64 t; cvta.to.shared.u64 t, %1; cvt.u32.u64 %0, t; }" : "=r"(a) : "l"(p));
    return a;
}
__device__ __forceinline__ void mma_tf32(float* d, const uint32_t* a, const uint32_t* b)
{
    asm volatile(
        "mma.sync.aligned.m16n8k8.row.col.f32.tf32.tf32.f32 "
        "{%0,%1,%2,%3}, {%4,%5,%6,%7}, {%8,%9}, {%0,%1,%2,%3};\n"
        : "+f"(d[0]), "+f"(d[1]), "+f"(d[2]), "+f"(d[3])
        : "r"(a[0]), "r"(a[1]), "r"(a[2]), "r"(a[3]), "r"(b[0]), "r"(b[1]));
}
__device__ __forceinline__ void ldsm_x4(uint32_t* r, uint32_t addr)
{
    asm volatile("ldmatrix.sync.aligned.m8n8.x4.shared.b16 {%0,%1,%2,%3}, [%4];"
        : "=r"(r[0]), "=r"(r[1]), "=r"(r[2]), "=r"(r[3]) : "r"(addr));
}
__device__ __forceinline__ void ldsm_x2(uint32_t* r, uint32_t addr)
{
    asm volatile("ldmatrix.sync.aligned.m8n8.x2.shared.b16 {%0,%1}, [%2];"
        : "=r"(r[0]), "=r"(r[1]) : "r"(addr));
}
__device__ __forceinline__ void cp16(uint32_t saddr, const void* gptr)
{
    asm volatile("cp.async.cg.shared.global [%0], [%1], 16;" :: "r"(saddr), "l"(gptr));
}
#define CP_COMMIT() asm volatile("cp.async.commit_group;" ::: "memory")
#define CP_WAIT(n)  asm volatile("cp.async.wait_group %0;" :: "n"(n) : "memory")
__device__ __forceinline__ uint32_t f2tf(float f)
{
    uint32_t u;
    asm("cvt.rna.tf32.f32 %0, %1;" : "=r"(u) : "f"(f));
    return u;
}
__device__ __forceinline__ uint4 cvt4(float4 v)
{
    uint4 o;
    o.x = f2tf(v.x); o.y = f2tf(v.y); o.z = f2tf(v.z); o.w = f2tf(v.w);
    return o;
}

#define SMSTRIDE 36
#define SM_TILE  (128 * SMSTRIDE)
#define SM_TOTAL (4 * SM_TILE * 4)

// one 128x128x32 block-step via LDSM fragment loads
__device__ __forceinline__ void mma_block(uint32_t sA, uint32_t sB,
                                          int wm, int wn, int lane, float acc[4][4][4])
{
    uint32_t aoff = sA + (uint32_t)(((wm * 64 + (lane & 15)) * SMSTRIDE + (lane >> 4) * 4) * 4);
    uint32_t boff = sB + (uint32_t)(((wn * 32 + (lane & 7)) * SMSTRIDE + ((lane >> 3) & 1) * 4) * 4);
    #pragma unroll
    for (int ks = 0; ks < 4; ks++) {
        uint32_t a[4][4], b[4][2];
        #pragma unroll
        for (int mi = 0; mi < 4; mi++)
            ldsm_x4(a[mi], aoff + (uint32_t)((mi * 16 * SMSTRIDE + ks * 8) * 4));
        #pragma unroll
        for (int ni = 0; ni < 4; ni++)
            ldsm_x2(b[ni], boff + (uint32_t)((ni * 8 * SMSTRIDE + ks * 8) * 4));
        #pragma unroll
        for (int mi = 0; mi < 4; mi++)
            #pragma unroll
            for (int ni = 0; ni < 4; ni++)
                mma_tf32(acc[mi][ni], a[mi], b[ni]);
    }
}

// ================= dense tf32 GEMM =================
__global__ __launch_bounds__(256) void tf32_gemm(
    const float* __restrict__ A, const float* __restrict__ Bt,
    const float* __restrict__ bias, const float* __restrict__ res,
    float* __restrict__ C, int M, int N, int K, int do_relu)
{
    extern __shared__ float sm[];
    uint32_t smb = smem_u32(sm);
    int tid = threadIdx.x;
    int bm = blockIdx.x, bn = blockIdx.y;
    int lane = tid & 31, wid = tid >> 5;
    int wm = wid >> 2, wn = wid & 3;
    int r0 = tid >> 3, c4 = tid & 7;

    const float* Ab = A + (size_t)(bm * 128 + r0) * K + c4 * 4;
    const float* Bb = Bt + (size_t)(bn * 128 + r0) * K + c4 * 4;
    uint32_t soff = (uint32_t)((r0 * SMSTRIDE + c4 * 4) * 4);

    float acc[4][4][4];
    #pragma unroll
    for (int i = 0; i < 4; i++)
        #pragma unroll
        for (int j = 0; j < 4; j++)
            #pragma unroll
            for (int t = 0; t < 4; t++) acc[i][j][t] = 0.f;

    int NC = K >> 5;
    float4 ra[4];
    #pragma unroll
    for (int i = 0; i < 4; i++)
        cp16(smb + (uint32_t)(SM_TILE * 4) + soff + (uint32_t)(i * 32 * SMSTRIDE * 4),
             Bb + (size_t)i * 32 * K);
    CP_COMMIT();
    #pragma unroll
    for (int i = 0; i < 4; i++)
        ra[i] = *(const float4*)(Ab + (size_t)i * 32 * K);
    #pragma unroll
    for (int i = 0; i < 4; i++)
        *(uint4*)&sm[(r0 + i * 32) * SMSTRIDE + c4 * 4] = cvt4(ra[i]);
    CP_WAIT(0);
    __syncthreads();

    for (int kc = 0; kc < NC; kc++) {
        int buf = kc & 1;
        int nb = buf ^ 1;
        if (kc + 1 < NC) {
            int k0 = (kc + 1) << 5;
            #pragma unroll
            for (int i = 0; i < 4; i++)
                cp16(smb + (uint32_t)((nb * 2 * SM_TILE + SM_TILE) * 4) + soff
                         + (uint32_t)(i * 32 * SMSTRIDE * 4),
                     Bb + (size_t)i * 32 * K + k0);
            CP_COMMIT();
            #pragma unroll
            for (int i = 0; i < 4; i++)
                ra[i] = *(const float4*)(Ab + (size_t)i * 32 * K + k0);
        }
        mma_block(smb + (uint32_t)(buf * 2 * SM_TILE * 4),
                  smb + (uint32_t)((buf * 2 * SM_TILE + SM_TILE) * 4), wm, wn, lane, acc);
        if (kc + 1 < NC) {
            #pragma unroll
            for (int i = 0; i < 4; i++)
                *(uint4*)&sm[nb * 2 * SM_TILE + (r0 + i * 32) * SMSTRIDE + c4 * 4] = cvt4(ra[i]);
            CP_WAIT(0);
            __syncthreads();
        }
    }

    int tg = lane & 3, gp = lane >> 2;
    #pragma unroll
    for (int mi = 0; mi < 4; mi++) {
        #pragma unroll
        for (int ni = 0; ni < 4; ni++) {
            int rl = wm * 64 + mi * 16 + gp;
            int col = bn * 128 + wn * 32 + ni * 8 + tg * 2;
            float2 bv = make_float2(0.f, 0.f);
            if (bias) bv = *(const float2*)(bias + col);
            #pragma unroll
            for (int h = 0; h < 2; h++) {
                size_t rowg = (size_t)bm * 128 + rl + h * 8;
                float2 v = make_float2(acc[mi][ni][2 * h] + bv.x, acc[mi][ni][2 * h + 1] + bv.y);
                if (res) {
                    float2 rv = *(const float2*)(res + rowg * N + col);
                    v.x += rv.x; v.y += rv.y;
                }
                if (do_relu) { v.x = fmaxf(v.x, 0.f); v.y = fmaxf(v.y, 0.f); }
                *(float2*)(C + rowg * N + col) = v;
            }
        }
    }
}

// ================= DAG MLP fused =================
__global__ __launch_bounds__(256) void tf32_dag_mlp(
    const float* __restrict__ E, const int* __restrict__ leaves, const int* __restrict__ anc,
    const float* __restrict__ dmask, const float* __restrict__ w1T,
    const float* __restrict__ b1, const float* __restrict__ w2, float* __restrict__ scores)
{
    extern __shared__ float sm[];
    uint32_t smb = smem_u32(sm);
    int tid = threadIdx.x;
    int bm = blockIdx.x, bn = blockIdx.y;
    int lane = tid & 31, wid = tid >> 5;
    int wm = wid >> 2, wn = wid & 3;
    int r0 = tid >> 3, c4 = tid & 7;

    int nl[4], na[4];
    #pragma unroll
    for (int i = 0; i < 4; i++) {
        int m = bm * 128 + r0 + i * 32;
        nl[i] = leaves[m]; na[i] = anc[m];
    }
    const float* Bb = w1T + (size_t)(bn * 128 + r0) * 512 + c4 * 4;
    uint32_t soff = (uint32_t)((r0 * SMSTRIDE + c4 * 4) * 4);

    float acc[4][4][4];
    #pragma unroll
    for (int i = 0; i < 4; i++)
        #pragma unroll
        for (int j = 0; j < 4; j++)
            #pragma unroll
            for (int t = 0; t < 4; t++) acc[i][j][t] = 0.f;

    const int NC = 16;
    float4 ra[4];
    #pragma unroll
    for (int i = 0; i < 4; i++)
        cp16(smb + (uint32_t)(SM_TILE * 4) + soff + (uint32_t)(i * 32 * SMSTRIDE * 4),
             Bb + (size_t)i * 32 * 512);
    CP_COMMIT();
    #pragma unroll
    for (int i = 0; i < 4; i++)
        ra[i] = *(const float4*)(E + (size_t)nl[i] * 256 + c4 * 4);
    #pragma unroll
    for (int i = 0; i < 4; i++)
        *(uint4*)&sm[(r0 + i * 32) * SMSTRIDE + c4 * 4] = cvt4(ra[i]);
    CP_WAIT(0);
    __syncthreads();

    for (int kc = 0; kc < NC; kc++) {
        int buf = kc & 1;
        int nb = buf ^ 1;
        if (kc + 1 < NC) {
            int k0 = (kc + 1) << 5;
            int kk = k0 & 255;
            bool first = k0 < 256;
            #pragma unroll
            for (int i = 0; i < 4; i++)
                cp16(smb + (uint32_t)((nb * 2 * SM_TILE + SM_TILE) * 4) + soff
                         + (uint32_t)(i * 32 * SMSTRIDE * 4),
                     Bb + (size_t)i * 32 * 512 + k0);
            CP_COMMIT();
            #pragma unroll
            for (int i = 0; i < 4; i++) {
                int node = first ? nl[i] : na[i];
                ra[i] = *(const float4*)(E + (size_t)node * 256 + kk + c4 * 4);
            }
        }
        mma_block(smb + (uint32_t)(buf * 2 * SM_TILE * 4),
                  smb + (uint32_t)((buf * 2 * SM_TILE + SM_TILE) * 4), wm, wn, lane, acc);
        if (kc + 1 < NC) {
            #pragma unroll
            for (int i = 0; i < 4; i++)
                *(uint4*)&sm[nb * 2 * SM_TILE + (r0 + i * 32) * SMSTRIDE + c4 * 4] = cvt4(ra[i]);
            CP_WAIT(0);
            __syncthreads();
        }
    }

    int tg = lane & 3, gp = lane >> 2;
    float2 bv[4], w2v[4];
    #pragma unroll
    for (int ni = 0; ni < 4; ni++) {
        int col = bn * 128 + wn * 32 + ni * 8 + tg * 2;
        bv[ni] = *(const float2*)(b1 + col);
        w2v[ni] = *(const float2*)(w2 + col);
    }
    #pragma unroll
    for (int mi = 0; mi < 4; mi++) {
        int rl = wm * 64 + mi * 16 + gp;
        float mk0 = dmask[bm * 128 + rl];
        float mk1 = dmask[bm * 128 + rl + 8];
        float p0 = 0.f, p1 = 0.f;
        #pragma unroll
        for (int ni = 0; ni < 4; ni++) {
            float v0x = fmaxf(mk0 * acc[mi][ni][0] + bv[ni].x, 0.f);
            float v0y = fmaxf(mk0 * acc[mi][ni][1] + bv[ni].y, 0.f);
            float v1x = fmaxf(mk1 * acc[mi][ni][2] + bv[ni].x, 0.f);
            float v1y = fmaxf(mk1 * acc[mi][ni][3] + bv[ni].y, 0.f);
            p0 += v0x * w2v[ni].x + v0y * w2v[ni].y;
            p1 += v1x * w2v[ni].x + v1y * w2v[ni].y;
        }
        p0 += __shfl_xor_sync(0xffffffffu, p0, 1);
        p0 += __shfl_xor_sync(0xffffffffu, p0, 2);
        p1 += __shfl_xor_sync(0xffffffffu, p1, 1);
        p1 += __shfl_xor_sync(0xffffffffu, p1, 2);
        if (tg == 0) {
            atomicAdd(scores + bm * 128 + rl, p0);
            atomicAdd(scores + bm * 128 + rl + 8, p1);
        }
    }
}

// ================= zero scores =================
__global__ __launch_bounds__(256) void zero_scores(float* s)
{
    int i = blockIdx.x * 256 + threadIdx.x;
    if (i < CA_) s[i] = 0.f;
}

// ================= batched transpose (stores tf32-RNA-rounded weights) =================
struct TransDesc { const float* src; float* dst; int R, C; };
struct TransArgs { TransDesc d[13]; };
__global__ __launch_bounds__(256) void transpose_all(TransArgs args)
{
    TransDesc t = args.d[blockIdx.z];
    if (blockIdx.x * 32 >= t.C || blockIdx.y * 32 >= t.R) return;
    __shared__ float tt[32][33];
    int x = threadIdx.x & 31, y0 = threadIdx.x >> 5;
    int c = blockIdx.x * 32 + x;
    #pragma unroll
    for (int i = 0; i < 32; i += 8)
        tt[y0 + i][x] = t.src[(size_t)(blockIdx.y * 32 + y0 + i) * t.C + c];
    __syncthreads();
    int rr = blockIdx.y * 32 + x;
    #pragma unroll
    for (int i = 0; i < 32; i += 8)
        t.dst[(size_t)(blockIdx.x * 32 + y0 + i) * t.R + rr] =
            __uint_as_float(f2tf(tt[x][y0 + i]));
}

// ================= DAG reduce =================
__global__ __launch_bounds__(256) void dag_reduce_kernel(
    const float* __restrict__ scores, const float* __restrict__ b2,
    const int* __restrict__ anc, const float* __restrict__ dmask,
    const float* __restrict__ E, float* __restrict__ dict)
{
    int warp = threadIdx.x >> 5, lane = threadIdx.x & 31;
    if (blockIdx.x == 0) dict[threadIdx.x] = 0.f;
    int c = blockIdx.x * 8 + warp;
    if (c >= C_) return;
    float p[8];
    float esum = 0.f;
    float b2v = b2[0];
    #pragma unroll
    for (int a = 0; a < 8; a++) {
        float mkk = dmask[c * 8 + a];
        float s = scores[c * 8 + a] + b2v + (1.f - mkk) * VERY_NEG;
        float e = __expf(s);
        esum += e;
        p[a] = e * mkk;
    }
    float inv = 1.f / esum;
    int nodes[8];
    #pragma unroll
    for (int a = 0; a < 8; a++) nodes[a] = anc[c * 8 + a];
    for (int t = lane; t < 256; t += 32) {
        float o = 0.f;
        #pragma unroll
        for (int a = 0; a < 8; a++) o += p[a] * E[(size_t)nodes[a] * 256 + t];
        dict[(size_t)(c + 1) * 256 + t] = o * inv;
    }
}

// ================= gathers (split) =================
__global__ __launch_bounds__(256) void gather_v(
    const int* __restrict__ ids, const float* __restrict__ Ein, float* __restrict__ xv)
{
    int bs = blockIdx.x;
    int t = threadIdx.x;
    int id = ids[bs];
    xv[(size_t)bs * 256 + t] = Ein[(size_t)id * 256 + t];
}
__global__ __launch_bounds__(256) void gather_d(
    const int* __restrict__ ids, const float* __restrict__ dict, float* __restrict__ xd)
{
    int bs = blockIdx.x;
    int t = threadIdx.x;
    int id = ids[bs];
    xd[(size_t)bs * 256 + t] = dict[(size_t)id * 256 + t];
}

// ================= tensor-core attention (LDSM fragment loads) =================
#define ATT_SMEM ((9216 + 8320 + 9216 + 256) * 4)
__global__ __launch_bounds__(256, 1) void attn_mma(
    const float* __restrict__ qkv, const float* __restrict__ code_mask, float* __restrict__ ctx)
{
    extern __shared__ float sm[];
    uint32_t smb = smem_u32(sm);
    float* Ks = sm;
    float* Vt = sm + 9216;
    float* Ps = sm + 9216 + 8320;
    float* Ms = sm + 9216 + 8320 + 9216;
    int bh = blockIdx.x;
    int b = bh >> 3, h = bh & 7;
    int tid = threadIdx.x, lane = tid & 31, wid = tid >> 5;
    int tg = lane & 3, gp = lane >> 2;
    int w0 = wid * 32;
    const size_t qb = (size_t)b * 256 * 768 + h * 32;

    uint32_t aoffP = smb + (uint32_t)((9216 + 8320) * 4)
                   + (uint32_t)((((lane & 15)) * 36 + (lane >> 4) * 4) * 4);
    uint32_t boffK = smb + (uint32_t)((((lane & 7)) * 36 + ((lane >> 3) & 1) * 4) * 4);
    uint32_t boffV = smb + (uint32_t)(9216 * 4)
                   + (uint32_t)((((lane & 7)) * 260 + ((lane >> 3) & 1) * 4) * 4);

    {
        int r = tid >> 3, c4 = tid & 7;
        #pragma unroll
        for (int i = 0; i < 8; i++) {
            int row = r + i * 32;
            float4 kv = *(const float4*)(qkv + qb + 256 + (size_t)row * 768 + c4 * 4);
            float4 qv = *(const float4*)(qkv + qb +       (size_t)row * 768 + c4 * 4);
            *(uint4*)&Ks[row * 36 + c4 * 4] = cvt4(kv);
            *(uint4*)&Ps[row * 36 + c4 * 4] = cvt4(qv);
        }
        int j = tid;
        #pragma unroll
        for (int d4 = 0; d4 < 8; d4++) {
            float4 vv = *(const float4*)(qkv + qb + 512 + (size_t)j * 768 + d4 * 4);
            uint4 vt = cvt4(vv);
            Vt[(d4 * 4 + 0) * 260 + j] = __uint_as_float(vt.x);
            Vt[(d4 * 4 + 1) * 260 + j] = __uint_as_float(vt.y);
            Vt[(d4 * 4 + 2) * 260 + j] = __uint_as_float(vt.z);
            Vt[(d4 * 4 + 3) * 260 + j] = __uint_as_float(vt.w);
        }
        Ms[tid] = (1.f - code_mask[b * 256 + tid]) * VERY_NEG;
    }
    __syncthreads();

    uint32_t qa[2][4][4];
    #pragma unroll
    for (int mi = 0; mi < 2; mi++)
        #pragma unroll
        for (int ks = 0; ks < 4; ks++)
            ldsm_x4(qa[mi][ks], aoffP + (uint32_t)(((w0 + mi * 16) * 36 + ks * 8) * 4));

    float oacc[2][4][4];
    #pragma unroll
    for (int i = 0; i < 2; i++)
        #pragma unroll
        for (int j = 0; j < 4; j++)
            #pragma unroll
            for (int t = 0; t < 4; t++) oacc[i][j][t] = 0.f;
    float lr[4] = {0.f, 0.f, 0.f, 0.f};
    const float scale = 0.17677669529663687f;

    for (int jc = 0; jc < 8; jc++) {
        int j0 = jc * 32;
        float sacc[2][4][4];
        #pragma unroll
        for (int i = 0; i < 2; i++)
            #pragma unroll
            for (int j = 0; j < 4; j++)
                #pragma unroll
                for (int t = 0; t < 4; t++) sacc[i][j][t] = 0.f;
        #pragma unroll
        for (int ks = 0; ks < 4; ks++) {
            uint32_t bfr[4][2];
            #pragma unroll
            for (int ni = 0; ni < 4; ni++)
                ldsm_x2(bfr[ni], boffK + (uint32_t)(((j0 + ni * 8) * 36 + ks * 8) * 4));
            #pragma unroll
            for (int mi = 0; mi < 2; mi++)
                #pragma unroll
                for (int ni = 0; ni < 4; ni++)
                    mma_tf32(sacc[mi][ni], qa[mi][ks], bfr[ni]);
        }
        __syncwarp();
        #pragma unroll
        for (int mi = 0; mi < 2; mi++) {
            int row = w0 + mi * 16 + gp;
            #pragma unroll
            for (int ni = 0; ni < 4; ni++) {
                int colg = j0 + ni * 8 + 2 * tg;
                float m0 = Ms[colg], m1 = Ms[colg + 1];
                float e0 = __expf(sacc[mi][ni][0] * scale + m0);
                float e1 = __expf(sacc[mi][ni][1] * scale + m1);
                float e2 = __expf(sacc[mi][ni][2] * scale + m0);
                float e3 = __expf(sacc[mi][ni][3] * scale + m1);
                lr[mi * 2 + 0] += e0 + e1;
                lr[mi * 2 + 1] += e2 + e3;
                int cl = ni * 8 + 2 * tg;
                *(float2*)&Ps[row * 36 + cl] =
                    make_float2(__uint_as_float(f2tf(e0)), __uint_as_float(f2tf(e1)));
                *(float2*)&Ps[(row + 8) * 36 + cl] =
                    make_float2(__uint_as_float(f2tf(e2)), __uint_as_float(f2tf(e3)));
            }
        }
        __syncwarp();
        #pragma unroll
        for (int ks2 = 0; ks2 < 4; ks2++) {
            uint32_t pa[2][4], bvv[4][2];
            #pragma unroll
            for (int mi = 0; mi < 2; mi++)
                ldsm_x4(pa[mi], aoffP + (uint32_t)(((w0 + mi * 16) * 36 + ks2 * 8) * 4));
            #pragma unroll
            for (int ni = 0; ni < 4; ni++)
                ldsm_x2(bvv[ni], boffV + (uint32_t)(((ni * 8) * 260 + j0 + ks2 * 8) * 4));
            #pragma unroll
            for (int mi = 0; mi < 2; mi++)
                #pragma unroll
                for (int ni = 0; ni < 4; ni++)
                    mma_tf32(oacc[mi][ni], pa[mi], bvv[ni]);
        }
        __syncwarp();
    }

    #pragma unroll
    for (int i = 0; i < 4; i++) {
        lr[i] += __shfl_xor_sync(0xffffffffu, lr[i], 1);
        lr[i] += __shfl_xor_sync(0xffffffffu, lr[i], 2);
    }
    #pragma unroll
    for (int mi = 0; mi < 2; mi++) {
        float inv0 = 1.f / lr[mi * 2 + 0];
        float inv1 = 1.f / lr[mi * 2 + 1];
        int row = w0 + mi * 16 + gp;
        #pragma unroll
        for (int ni = 0; ni < 4; ni++) {
            int col = h * 32 + ni * 8 + 2 * tg;
            *(float2*)(ctx + (size_t)(b * 256 + row) * 256 + col) =
                make_float2(oacc[mi][ni][0] * inv0, oacc[mi][ni][1] * inv0);
            *(float2*)(ctx + (size_t)(b * 256 + row + 8) * 256 + col) =
                make_float2(oacc[mi][ni][2] * inv1, oacc[mi][ni][3] * inv1);
        }
    }
}

// ================= pooling =================
__global__ __launch_bounds__(256) void pool_kernel(
    const float* __restrict__ x, const float* __restrict__ pw, const float* __restrict__ pb,
    const float* __restrict__ code_mask, float* __restrict__ out)
{
    __shared__ float sp[256], sq[256];
    int b = blockIdx.x;
    int j = threadIdx.x;
    const float* xr = x + ((size_t)b * 256 + j) * 256;
    float s = 0.f;
    for (int t = 0; t < 256; t++) s += xr[t] * pw[t];
    s += pb[0] + (1.f - code_mask[b * 256 + j]) * VERY_NEG;
    sq[j] = s;
    __syncthreads();
    for (int o = 128; o; o >>= 1) { if (j < o) sq[j] = fmaxf(sq[j], sq[j + o]); __syncthreads(); }
    float mx = sq[0];
    __syncthreads();
    float e = __expf(s - mx);
    sp[j] = e; sq[j] = e;
    __syncthreads();
    for (int o = 128; o; o >>= 1) { if (j < o) sq[j] += sq[j + o]; __syncthreads(); }
    float inv = 1.f / sq[0];
    __syncthreads();
    float o = 0.f;
    for (int t = 0; t < 256; t++) o += sp[t] * x[((size_t)b * 256 + t) * 256 + j];
    out[(size_t)b * 256 + j] = o * inv;
}

// ================= launch =================
static cudaStream_t g_s2 = nullptr;
static cudaEvent_t  g_ev1 = nullptr, g_ev2 = nullptr;

extern "C" void kernel_launch(void* const* d_in, const int* in_sizes, int n_in,
                              void* d_out, int out_size)
{
    const int*   input_ids = (const int*)  d_in[0];
    const float* code_mask = (const float*)d_in[1];
    const int*   leaves    = (const int*)  d_in[2];
    const int*   anc       = (const int*)  d_in[3];
    const float* dmask     = (const float*)d_in[4];
    const float* Einit     = (const float*)d_in[5];
    const float* Einp      = (const float*)d_in[6];
    const float* aw1       = (const float*)d_in[7];
    const float* ab1       = (const float*)d_in[8];
    const float* aw2       = (const float*)d_in[9];
    const float* ab2       = (const float*)d_in[10];
    const float* pw        = (const float*)d_in[11];
    const float* pb        = (const float*)d_in[12];
    float* out = (float*)d_out;

    float *dict, *xv, *xd, *t1, *qkv, *ctx, *ff, *wT, *scores;
    cudaGetSymbolAddress((void**)&dict,   g_dict);
    cudaGetSymbolAddress((void**)&xv,     g_xv);
    cudaGetSymbolAddress((void**)&xd,     g_xd);
    cudaGetSymbolAddress((void**)&t1,     g_t1);
    cudaGetSymbolAddress((void**)&qkv,    g_qkv);
    cudaGetSymbolAddress((void**)&ctx,    g_ctx);
    cudaGetSymbolAddress((void**)&ff,     g_ff);
    cudaGetSymbolAddress((void**)&wT,     g_wT);
    cudaGetSymbolAddress((void**)&scores, g_scores);

    if (!g_s2) {
        cudaStreamCreateWithFlags(&g_s2, cudaStreamNonBlocking);
        cudaEventCreateWithFlags(&g_ev1, cudaEventDisableTiming);
        cudaEventCreateWithFlags(&g_ev2, cudaEventDisableTiming);
    }

    cudaFuncSetAttribute(tf32_gemm,    cudaFuncAttributeMaxDynamicSharedMemorySize, SM_TOTAL);
    cudaFuncSetAttribute(tf32_dag_mlp, cudaFuncAttributeMaxDynamicSharedMemorySize, SM_TOTAL);
    cudaFuncSetAttribute(attn_mma,     cudaFuncAttributeMaxDynamicSharedMemorySize, ATT_SMEM);

    TransArgs ta;
    ta.d[0] = {aw1, wT + 1572864, 512, 256};
    for (int l = 0; l < 2; l++) {
        int wb = 13 + 8 * l;
        float* base = wT + l * 786432;
        ta.d[1 + 6 * l + 0] = {(const float*)d_in[wb + 0], base + 0,      256, 256};
        ta.d[1 + 6 * l + 1] = {(const float*)d_in[wb + 1], base + 65536,  256, 256};
        ta.d[1 + 6 * l + 2] = {(const float*)d_in[wb + 2], base + 131072, 256, 256};
        ta.d[1 + 6 * l + 3] = {(const float*)d_in[wb + 3], base + 196608, 256, 256};
        ta.d[1 + 6 * l + 4] = {(const float*)d_in[wb + 4], base + 262144, 256, 1024};
        ta.d[1 + 6 * l + 5] = {(const float*)d_in[wb + 6], base + 524288, 1024, 256};
    }
    transpose_all<<<dim3(32, 32, 13), 256>>>(ta);

    // ---- fork: DAG pipeline on side stream ----
    cudaEventRecord(g_ev1, 0);
    cudaStreamWaitEvent(g_s2, g_ev1, 0);
    zero_scores<<<(CA_ + 255) / 256, 256, 0, g_s2>>>(scores);
    tf32_dag_mlp<<<dim3(CA_ / 128, 2), 256, SM_TOTAL, g_s2>>>(Einit, leaves, anc, dmask,
                                                              wT + 1572864, ab1, aw2, scores);
    dag_reduce_kernel<<<C_ / 8, 256, 0, g_s2>>>(scores, ab2, anc, dmask, Einit, dict);
    cudaEventRecord(g_ev2, g_s2);

    // ---- main stream: visit encoder (independent of DAG pipeline) ----
    gather_v<<<BS_, 256>>>(input_ids, Einp, xv);

    auto encoder = [&](const float* X, int l, float* O) {
        float* base = wT + l * 786432;
        const float* fb1 = (const float*)d_in[13 + 8 * l + 5];
        const float* fb2 = (const float*)d_in[13 + 8 * l + 7];
        tf32_gemm<<<dim3(BS_ / 128, 6), 256, SM_TOTAL>>>(X, base + 0, nullptr, nullptr,
                                                         qkv, BS_, 768, 256, 0);
        attn_mma<<<B_ * 8, 256, ATT_SMEM>>>(qkv, code_mask, ctx);
        tf32_gemm<<<dim3(BS_ / 128, 2), 256, SM_TOTAL>>>(ctx, base + 196608, nullptr, X,
                                                         t1, BS_, 256, 256, 0);
        tf32_gemm<<<dim3(BS_ / 128, 8), 256, SM_TOTAL>>>(t1, base + 262144, fb1, nullptr,
                                                         ff, BS_, 1024, 256, 1);
        tf32_gemm<<<dim3(BS_ / 128, 2), 256, SM_TOTAL>>>(ff, base + 524288, fb2, t1,
                                                         O, BS_, 256, 1024, 0);
    };
    encoder(xv, 0, out);

    // ---- join: DAG encoder needs dict ----
    cudaStreamWaitEvent(0, g_ev2, 0);
    gather_d<<<BS_, 256>>>(input_ids, dict, xd);
    encoder(xd, 1, xv);

    pool_kernel<<<B_, 256>>>(xv, pw, pb, code_mask, out + (size_t)BS_ * H_);
}

// round 14
// speedup vs baseline: 1.4456x; 1.4456x over previous
#include <cuda_runtime.h>
#include <cuda_fp16.h>
#include <cstdint>
#include <cstddef>

#define VERY_NEG -1e30f
#define B_   128
#define S_   256
#define H_   256
#define C_   20000
#define A_   8
#define BS_  (B_*S_)      // 32768
#define CA_  (C_*A_)      // 160000

// ================= scratch =================
__device__ float g_dict[(C_+1)*H_];
__device__ float g_xv[BS_*H_];
__device__ float g_xd[BS_*H_];
__device__ float g_t1[BS_*H_];
__device__ float g_qkv[BS_*768];
__device__ float g_ctx[BS_*H_];
__device__ float g_ff[BS_*4*H_];
__device__ __align__(16) __half g_wTh[1703936 + 256];  // fp16 transposed weights
__device__ float g_scores[CA_];

// ================= PTX helpers =================
__device__ __forceinline__ uint32_t smem_u32(const void* p) {
    uint32_t a;
    asm("{ .reg .u64 t; cvta.to.shared.u64 t, %1; cvt.u32.u64 %0, t; }" : "=r"(a) : "l"(p));
    return a;
}
__device__ __forceinline__ void mma_f16(float* d, const uint32_t* a, const uint32_t* b)
{
    asm volatile(
        "mma.sync.aligned.m16n8k16.row.col.f32.f16.f16.f32 "
        "{%0,%1,%2,%3}, {%4,%5,%6,%7}, {%8,%9}, {%0,%1,%2,%3};\n"
        : "+f"(d[0]), "+f"(d[1]), "+f"(d[2]), "+f"(d[3])
        : "r"(a[0]), "r"(a[1]), "r"(a[2]), "r"(a[3]), "r"(b[0]), "r"(b[1]));
}
__device__ __forceinline__ void mma_tf32(float* d, const uint32_t* a, const uint32_t* b)
{
    asm volatile(
        "mma.sync.aligned.m16n8k8.row.col.f32.tf32.tf32.f32 "
        "{%0,%1,%2,%3}, {%4,%5,%6,%7}, {%8,%9}, {%0,%1,%2,%3};\n"
        : "+f"(d[0]), "+f"(d[1]), "+f"(d[2]), "+f"(d[3])
        : "r"(a[0]), "r"(a[1]), "r"(a[2]), "r"(a[3]), "r"(b[0]), "r"(b[1]));
}
__device__ __forceinline__ void ldsm_x4(uint32_t* r, uint32_t addr)
{
    asm volatile("ldmatrix.sync.aligned.m8n8.x4.shared.b16 {%0,%1,%2,%3}, [%4];"
        : "=r"(r[0]), "=r"(r[1]), "=r"(r[2]), "=r"(r[3]) : "r"(addr));
}
__device__ __forceinline__ void ldsm_x2(uint32_t* r, uint32_t addr)
{
    asm volatile("ldmatrix.sync.aligned.m8n8.x2.shared.b16 {%0,%1}, [%2];"
        : "=r"(r[0]), "=r"(r[1]) : "r"(addr));
}
__device__ __forceinline__ void cp16(uint32_t saddr, const void* gptr)
{
    asm volatile("cp.async.cg.shared.global [%0], [%1], 16;" :: "r"(saddr), "l"(gptr));
}
#define CP_COMMIT() asm volatile("cp.async.commit_group;" ::: "memory")
#define CP_WAIT(n)  asm volatile("cp.async.wait_group %0;" :: "n"(n) : "memory")
__device__ __forceinline__ uint32_t f2tf(float f)
{
    uint32_t u;
    asm("cvt.rna.tf32.f32 %0, %1;" : "=r"(u) : "f"(f));
    return u;
}
__device__ __forceinline__ uint4 cvt4(float4 v)
{
    uint4 o;
    o.x = f2tf(v.x); o.y = f2tf(v.y); o.z = f2tf(v.z); o.w = f2tf(v.w);
    return o;
}
__device__ __forceinline__ uint2 pack4h(float4 f)
{
    __half2 a = __floats2half2_rn(f.x, f.y);
    __half2 b = __floats2half2_rn(f.z, f.w);
    uint2 r;
    r.x = *(uint32_t*)&a;
    r.y = *(uint32_t*)&b;
    return r;
}

// ---- fp16 GEMM smem geometry: BK=64 halves, stride 72 halves ----
#define SH       72
#define SMT      (128 * SH * 2)            // bytes per tile (18432)
#define SM_TOTAL (4 * SMT)                 // [A0 B0 A1 B1] = 73728 B

// one 128x128x64 block-step via LDSM fp16 fragment loads
__device__ __forceinline__ void mma_block_f16(uint32_t sA, uint32_t sB,
                                              int wm, int wn, int lane, float acc[4][4][4])
{
    uint32_t aoff = sA + (uint32_t)(((wm * 64 + (lane & 15)) * SH + (lane >> 4) * 8) * 2);
    uint32_t boff = sB + (uint32_t)(((wn * 32 + (lane & 7)) * SH + ((lane >> 3) & 1) * 8) * 2);
    #pragma unroll
    for (int ks = 0; ks < 4; ks++) {
        uint32_t a[4][4], b[4][2];
        #pragma unroll
        for (int mi = 0; mi < 4; mi++)
            ldsm_x4(a[mi], aoff + (uint32_t)((mi * 16 * SH + ks * 16) * 2));
        #pragma unroll
        for (int ni = 0; ni < 4; ni++)
            ldsm_x2(b[ni], boff + (uint32_t)((ni * 8 * SH + ks * 16) * 2));
        #pragma unroll
        for (int mi = 0; mi < 4; mi++)
            #pragma unroll
            for (int ni = 0; ni < 4; ni++)
                mma_f16(acc[mi][ni], a[mi], b[ni]);
    }
}

// ================= dense fp16 GEMM: C[M,N] = op(A[M,K] @ Bth[N,K]^T) =================
// A (fp32 activations) staged via regs + fp16 pack; B (pre-converted fp16 weights) via cp.async.
__global__ __launch_bounds__(256) void f16_gemm(
    const float* __restrict__ A, const __half* __restrict__ Bth,
    const float* __restrict__ bias, const float* __restrict__ res,
    float* __restrict__ C, int M, int N, int K, int do_relu)
{
    extern __shared__ char smc[];
    uint32_t smb = smem_u32(smc);
    int tid = threadIdx.x;
    int bm = blockIdx.x, bn = blockIdx.y;
    int lane = tid & 31, wid = tid >> 5;
    int wm = wid >> 2, wn = wid & 3;
    int r0 = tid >> 3, c4 = tid & 7;

    const float*  Ab = A   + (size_t)(bm * 128 + r0) * K + c4 * 4;
    const __half* Bb = Bth + (size_t)(bn * 128 + r0) * K + c4 * 8;
    uint32_t sAoff = (uint32_t)((r0 * SH + c4 * 4) * 2);   // halves *2 bytes
    uint32_t sBoff = (uint32_t)((r0 * SH + c4 * 8) * 2);

    float acc[4][4][4];
    #pragma unroll
    for (int i = 0; i < 4; i++)
        #pragma unroll
        for (int j = 0; j < 4; j++)
            #pragma unroll
            for (int t = 0; t < 4; t++) acc[i][j][t] = 0.f;

    int NC = K >> 6;
    float4 fa[4][2];
    // prologue: chunk 0
    #pragma unroll
    for (int i = 0; i < 4; i++)
        cp16(smb + (uint32_t)SMT + sBoff + (uint32_t)(i * 32 * SH * 2), Bb + (size_t)i * 32 * K);
    CP_COMMIT();
    #pragma unroll
    for (int i = 0; i < 4; i++) {
        fa[i][0] = *(const float4*)(Ab + (size_t)i * 32 * K);
        fa[i][1] = *(const float4*)(Ab + (size_t)i * 32 * K + 32);
    }
    #pragma unroll
    for (int i = 0; i < 4; i++) {
        *(uint2*)(smc + sAoff + (uint32_t)(i * 32 * SH * 2))            = pack4h(fa[i][0]);
        *(uint2*)(smc + sAoff + (uint32_t)((i * 32 * SH + 32) * 2))     = pack4h(fa[i][1]);
    }
    CP_WAIT(0);
    __syncthreads();

    for (int kc = 0; kc < NC; kc++) {
        int buf = kc & 1;
        int nb = buf ^ 1;
        if (kc + 1 < NC) {
            int k0 = (kc + 1) << 6;
            #pragma unroll
            for (int i = 0; i < 4; i++)
                cp16(smb + (uint32_t)(nb * 2 * SMT + SMT) + sBoff + (uint32_t)(i * 32 * SH * 2),
                     Bb + (size_t)i * 32 * K + k0);
            CP_COMMIT();
            #pragma unroll
            for (int i = 0; i < 4; i++) {
                fa[i][0] = *(const float4*)(Ab + (size_t)i * 32 * K + k0);
                fa[i][1] = *(const float4*)(Ab + (size_t)i * 32 * K + k0 + 32);
            }
        }
        mma_block_f16(smb + (uint32_t)(buf * 2 * SMT),
                      smb + (uint32_t)(buf * 2 * SMT + SMT), wm, wn, lane, acc);
        if (kc + 1 < NC) {
            #pragma unroll
            for (int i = 0; i < 4; i++) {
                *(uint2*)(smc + (uint32_t)(nb * 2 * SMT) + sAoff + (uint32_t)(i * 32 * SH * 2))
                    = pack4h(fa[i][0]);
                *(uint2*)(smc + (uint32_t)(nb * 2 * SMT) + sAoff + (uint32_t)((i * 32 * SH + 32) * 2))
                    = pack4h(fa[i][1]);
            }
            CP_WAIT(0);
            __syncthreads();
        }
    }

    int tg = lane & 3, gp = lane >> 2;
    #pragma unroll
    for (int mi = 0; mi < 4; mi++) {
        #pragma unroll
        for (int ni = 0; ni < 4; ni++) {
            int rl = wm * 64 + mi * 16 + gp;
            int col = bn * 128 + wn * 32 + ni * 8 + tg * 2;
            float2 bv = make_float2(0.f, 0.f);
            if (bias) bv = *(const float2*)(bias + col);
            #pragma unroll
            for (int h = 0; h < 2; h++) {
                size_t rowg = (size_t)bm * 128 + rl + h * 8;
                float2 v = make_float2(acc[mi][ni][2 * h] + bv.x, acc[mi][ni][2 * h + 1] + bv.y);
                if (res) {
                    float2 rv = *(const float2*)(res + rowg * N + col);
                    v.x += rv.x; v.y += rv.y;
                }
                if (do_relu) { v.x = fmaxf(v.x, 0.f); v.y = fmaxf(v.y, 0.f); }
                *(float2*)(C + rowg * N + col) = v;
            }
        }
    }
}

// ================= DAG MLP fused (fp16): accumulate relu(...)·w2 into scores =================
__global__ __launch_bounds__(256) void f16_dag_mlp(
    const float* __restrict__ E, const int* __restrict__ leaves, const int* __restrict__ anc,
    const float* __restrict__ dmask, const __half* __restrict__ w1Th,
    const float* __restrict__ b1, const float* __restrict__ w2, float* __restrict__ scores)
{
    extern __shared__ char smc[];
    uint32_t smb = smem_u32(smc);
    int tid = threadIdx.x;
    int bm = blockIdx.x, bn = blockIdx.y;
    int lane = tid & 31, wid = tid >> 5;
    int wm = wid >> 2, wn = wid & 3;
    int r0 = tid >> 3, c4 = tid & 7;

    int nl[4], na[4];
    #pragma unroll
    for (int i = 0; i < 4; i++) {
        int m = bm * 128 + r0 + i * 32;
        nl[i] = leaves[m]; na[i] = anc[m];
    }
    const __half* Bb = w1Th + (size_t)(bn * 128 + r0) * 512 + c4 * 8;
    uint32_t sAoff = (uint32_t)((r0 * SH + c4 * 4) * 2);
    uint32_t sBoff = (uint32_t)((r0 * SH + c4 * 8) * 2);

    float acc[4][4][4];
    #pragma unroll
    for (int i = 0; i < 4; i++)
        #pragma unroll
        for (int j = 0; j < 4; j++)
            #pragma unroll
            for (int t = 0; t < 4; t++) acc[i][j][t] = 0.f;

    const int NC = 8;   // K = 512, BK = 64
    float4 fa[4][2];
    #pragma unroll
    for (int i = 0; i < 4; i++)
        cp16(smb + (uint32_t)SMT + sBoff + (uint32_t)(i * 32 * SH * 2), Bb + (size_t)i * 32 * 512);
    CP_COMMIT();
    #pragma unroll
    for (int i = 0; i < 4; i++) {
        const float* src = E + (size_t)nl[i] * 256 + c4 * 4;
        fa[i][0] = *(const float4*)(src);
        fa[i][1] = *(const float4*)(src + 32);
    }
    #pragma unroll
    for (int i = 0; i < 4; i++) {
        *(uint2*)(smc + sAoff + (uint32_t)(i * 32 * SH * 2))        = pack4h(fa[i][0]);
        *(uint2*)(smc + sAoff + (uint32_t)((i * 32 * SH + 32) * 2)) = pack4h(fa[i][1]);
    }
    CP_WAIT(0);
    __syncthreads();

    for (int kc = 0; kc < NC; kc++) {
        int buf = kc & 1;
        int nb = buf ^ 1;
        if (kc + 1 < NC) {
            int k0 = (kc + 1) << 6;
            int kk = k0 & 255;
            bool first = k0 < 256;
            #pragma unroll
            for (int i = 0; i < 4; i++)
                cp16(smb + (uint32_t)(nb * 2 * SMT + SMT) + sBoff + (uint32_t)(i * 32 * SH * 2),
                     Bb + (size_t)i * 32 * 512 + k0);
            CP_COMMIT();
            #pragma unroll
            for (int i = 0; i < 4; i++) {
                int node = first ? nl[i] : na[i];
                const float* src = E + (size_t)node * 256 + kk + c4 * 4;
                fa[i][0] = *(const float4*)(src);
                fa[i][1] = *(const float4*)(src + 32);
            }
        }
        mma_block_f16(smb + (uint32_t)(buf * 2 * SMT),
                      smb + (uint32_t)(buf * 2 * SMT + SMT), wm, wn, lane, acc);
        if (kc + 1 < NC) {
            #pragma unroll
            for (int i = 0; i < 4; i++) {
                *(uint2*)(smc + (uint32_t)(nb * 2 * SMT) + sAoff + (uint32_t)(i * 32 * SH * 2))
                    = pack4h(fa[i][0]);
                *(uint2*)(smc + (uint32_t)(nb * 2 * SMT) + sAoff + (uint32_t)((i * 32 * SH + 32) * 2))
                    = pack4h(fa[i][1]);
            }
            CP_WAIT(0);
            __syncthreads();
        }
    }

    int tg = lane & 3, gp = lane >> 2;
    float2 bv[4], w2v[4];
    #pragma unroll
    for (int ni = 0; ni < 4; ni++) {
        int col = bn * 128 + wn * 32 + ni * 8 + tg * 2;
        bv[ni] = *(const float2*)(b1 + col);
        w2v[ni] = *(const float2*)(w2 + col);
    }
    #pragma unroll
    for (int mi = 0; mi < 4; mi++) {
        int rl = wm * 64 + mi * 16 + gp;
        float mk0 = dmask[bm * 128 + rl];
        float mk1 = dmask[bm * 128 + rl + 8];
        float p0 = 0.f, p1 = 0.f;
        #pragma unroll
        for (int ni = 0; ni < 4; ni++) {
            float v0x = fmaxf(mk0 * acc[mi][ni][0] + bv[ni].x, 0.f);
            float v0y = fmaxf(mk0 * acc[mi][ni][1] + bv[ni].y, 0.f);
            float v1x = fmaxf(mk1 * acc[mi][ni][2] + bv[ni].x, 0.f);
            float v1y = fmaxf(mk1 * acc[mi][ni][3] + bv[ni].y, 0.f);
            p0 += v0x * w2v[ni].x + v0y * w2v[ni].y;
            p1 += v1x * w2v[ni].x + v1y * w2v[ni].y;
        }
        p0 += __shfl_xor_sync(0xffffffffu, p0, 1);
        p0 += __shfl_xor_sync(0xffffffffu, p0, 2);
        p1 += __shfl_xor_sync(0xffffffffu, p1, 1);
        p1 += __shfl_xor_sync(0xffffffffu, p1, 2);
        if (tg == 0) {
            atomicAdd(scores + bm * 128 + rl, p0);
            atomicAdd(scores + bm * 128 + rl + 8, p1);
        }
    }
}

// ================= zero scores =================
__global__ __launch_bounds__(256) void zero_scores(float* s)
{
    int i = blockIdx.x * 256 + threadIdx.x;
    if (i < CA_) s[i] = 0.f;
}

// ================= batched transpose -> fp16 =================
struct TransDesc { const float* src; __half* dst; int R, C; };
struct TransArgs { TransDesc d[13]; };
__global__ __launch_bounds__(256) void transpose_all(TransArgs args)
{
    TransDesc t = args.d[blockIdx.z];
    if (blockIdx.x * 32 >= t.C || blockIdx.y * 32 >= t.R) return;
    __shared__ float tt[32][33];
    int x = threadIdx.x & 31, y0 = threadIdx.x >> 5;
    int c = blockIdx.x * 32 + x;
    #pragma unroll
    for (int i = 0; i < 32; i += 8)
        tt[y0 + i][x] = t.src[(size_t)(blockIdx.y * 32 + y0 + i) * t.C + c];
    __syncthreads();
    int rr = blockIdx.y * 32 + x;
    #pragma unroll
    for (int i = 0; i < 32; i += 8)
        t.dst[(size_t)(blockIdx.x * 32 + y0 + i) * t.R + rr] = __float2half_rn(tt[x][y0 + i]);
}

// ================= DAG reduce =================
__global__ __launch_bounds__(256) void dag_reduce_kernel(
    const float* __restrict__ scores, const float* __restrict__ b2,
    const int* __restrict__ anc, const float* __restrict__ dmask,
    const float* __restrict__ E, float* __restrict__ dict)
{
    int warp = threadIdx.x >> 5, lane = threadIdx.x & 31;
    if (blockIdx.x == 0) dict[threadIdx.x] = 0.f;
    int c = blockIdx.x * 8 + warp;
    if (c >= C_) return;
    float p[8];
    float esum = 0.f;
    float b2v = b2[0];
    #pragma unroll
    for (int a = 0; a < 8; a++) {
        float mkk = dmask[c * 8 + a];
        float s = scores[c * 8 + a] + b2v + (1.f - mkk) * VERY_NEG;
        float e = __expf(s);
        esum += e;
        p[a] = e * mkk;
    }
    float inv = 1.f / esum;
    int nodes[8];
    #pragma unroll
    for (int a = 0; a < 8; a++) nodes[a] = anc[c * 8 + a];
    for (int t = lane; t < 256; t += 32) {
        float o = 0.f;
        #pragma unroll
        for (int a = 0; a < 8; a++) o += p[a] * E[(size_t)nodes[a] * 256 + t];
        dict[(size_t)(c + 1) * 256 + t] = o * inv;
    }
}

// ================= gather =================
__global__ __launch_bounds__(256) void gather_kernel(
    const int* __restrict__ ids, const float* __restrict__ Ein,
    const float* __restrict__ dict, float* __restrict__ xv, float* __restrict__ xd)
{
    int bs = blockIdx.x;
    int t = threadIdx.x;
    int id = ids[bs];
    size_t o = (size_t)bs * 256 + t;
    xv[o] = Ein[(size_t)id * 256 + t];
    xd[o] = dict[(size_t)id * 256 + t];
}

// ================= tensor-core attention (tf32, LDSM fragment loads) =================
#define ATT_SMEM ((9216 + 8320 + 9216 + 256) * 4)
__global__ __launch_bounds__(256, 1) void attn_mma(
    const float* __restrict__ qkv, const float* __restrict__ code_mask, float* __restrict__ ctx)
{
    extern __shared__ float sm[];
    uint32_t smb = smem_u32(sm);
    float* Ks = sm;
    float* Vt = sm + 9216;
    float* Ps = sm + 9216 + 8320;
    float* Ms = sm + 9216 + 8320 + 9216;
    int bh = blockIdx.x;
    int b = bh >> 3, h = bh & 7;
    int tid = threadIdx.x, lane = tid & 31, wid = tid >> 5;
    int tg = lane & 3, gp = lane >> 2;
    int w0 = wid * 32;
    const size_t qb = (size_t)b * 256 * 768 + h * 32;

    uint32_t aoffP = smb + (uint32_t)((9216 + 8320) * 4)
                   + (uint32_t)((((lane & 15)) * 36 + (lane >> 4) * 4) * 4);
    uint32_t boffK = smb + (uint32_t)((((lane & 7)) * 36 + ((lane >> 3) & 1) * 4) * 4);
    uint32_t boffV = smb + (uint32_t)(9216 * 4)
                   + (uint32_t)((((lane & 7)) * 260 + ((lane >> 3) & 1) * 4) * 4);

    {
        int r = tid >> 3, c4 = tid & 7;
        #pragma unroll
        for (int i = 0; i < 8; i++) {
            int row = r + i * 32;
            float4 kv = *(const float4*)(qkv + qb + 256 + (size_t)row * 768 + c4 * 4);
            float4 qv = *(const float4*)(qkv + qb +       (size_t)row * 768 + c4 * 4);
            *(uint4*)&Ks[row * 36 + c4 * 4] = cvt4(kv);
            *(uint4*)&Ps[row * 36 + c4 * 4] = cvt4(qv);
        }
        int j = tid;
        #pragma unroll
        for (int d4 = 0; d4 < 8; d4++) {
            float4 vv = *(const float4*)(qkv + qb + 512 + (size_t)j * 768 + d4 * 4);
            uint4 vt = cvt4(vv);
            Vt[(d4 * 4 + 0) * 260 + j] = __uint_as_float(vt.x);
            Vt[(d4 * 4 + 1) * 260 + j] = __uint_as_float(vt.y);
            Vt[(d4 * 4 + 2) * 260 + j] = __uint_as_float(vt.z);
            Vt[(d4 * 4 + 3) * 260 + j] = __uint_as_float(vt.w);
        }
        Ms[tid] = (1.f - code_mask[b * 256 + tid]) * VERY_NEG;
    }
    __syncthreads();

    uint32_t qa[2][4][4];
    #pragma unroll
    for (int mi = 0; mi < 2; mi++)
        #pragma unroll
        for (int ks = 0; ks < 4; ks++)
            ldsm_x4(qa[mi][ks], aoffP + (uint32_t)(((w0 + mi * 16) * 36 + ks * 8) * 4));

    float oacc[2][4][4];
    #pragma unroll
    for (int i = 0; i < 2; i++)
        #pragma unroll
        for (int j = 0; j < 4; j++)
            #pragma unroll
            for (int t = 0; t < 4; t++) oacc[i][j][t] = 0.f;
    float lr[4] = {0.f, 0.f, 0.f, 0.f};
    const float scale = 0.17677669529663687f;

    for (int jc = 0; jc < 8; jc++) {
        int j0 = jc * 32;
        float sacc[2][4][4];
        #pragma unroll
        for (int i = 0; i < 2; i++)
            #pragma unroll
            for (int j = 0; j < 4; j++)
                #pragma unroll
                for (int t = 0; t < 4; t++) sacc[i][j][t] = 0.f;
        #pragma unroll
        for (int ks = 0; ks < 4; ks++) {
            uint32_t bfr[4][2];
            #pragma unroll
            for (int ni = 0; ni < 4; ni++)
                ldsm_x2(bfr[ni], boffK + (uint32_t)(((j0 + ni * 8) * 36 + ks * 8) * 4));
            #pragma unroll
            for (int mi = 0; mi < 2; mi++)
                #pragma unroll
                for (int ni = 0; ni < 4; ni++)
                    mma_tf32(sacc[mi][ni], qa[mi][ks], bfr[ni]);
        }
        __syncwarp();
        #pragma unroll
        for (int mi = 0; mi < 2; mi++) {
            int row = w0 + mi * 16 + gp;
            #pragma unroll
            for (int ni = 0; ni < 4; ni++) {
                int colg = j0 + ni * 8 + 2 * tg;
                float m0 = Ms[colg], m1 = Ms[colg + 1];
                float e0 = __expf(sacc[mi][ni][0] * scale + m0);
                float e1 = __expf(sacc[mi][ni][1] * scale + m1);
                float e2 = __expf(sacc[mi][ni][2] * scale + m0);
                float e3 = __expf(sacc[mi][ni][3] * scale + m1);
                lr[mi * 2 + 0] += e0 + e1;
                lr[mi * 2 + 1] += e2 + e3;
                int cl = ni * 8 + 2 * tg;
                *(float2*)&Ps[row * 36 + cl] =
                    make_float2(__uint_as_float(f2tf(e0)), __uint_as_float(f2tf(e1)));
                *(float2*)&Ps[(row + 8) * 36 + cl] =
                    make_float2(__uint_as_float(f2tf(e2)), __uint_as_float(f2tf(e3)));
            }
        }
        __syncwarp();
        #pragma unroll
        for (int ks2 = 0; ks2 < 4; ks2++) {
            uint32_t pa[2][4], bvv[4][2];
            #pragma unroll
            for (int mi = 0; mi < 2; mi++)
                ldsm_x4(pa[mi], aoffP + (uint32_t)(((w0 + mi * 16) * 36 + ks2 * 8) * 4));
            #pragma unroll
            for (int ni = 0; ni < 4; ni++)
                ldsm_x2(bvv[ni], boffV + (uint32_t)(((ni * 8) * 260 + j0 + ks2 * 8) * 4));
            #pragma unroll
            for (int mi = 0; mi < 2; mi++)
                #pragma unroll
                for (int ni = 0; ni < 4; ni++)
                    mma_tf32(oacc[mi][ni], pa[mi], bvv[ni]);
        }
        __syncwarp();
    }

    #pragma unroll
    for (int i = 0; i < 4; i++) {
        lr[i] += __shfl_xor_sync(0xffffffffu, lr[i], 1);
        lr[i] += __shfl_xor_sync(0xffffffffu, lr[i], 2);
    }
    #pragma unroll
    for (int mi = 0; mi < 2; mi++) {
        float inv0 = 1.f / lr[mi * 2 + 0];
        float inv1 = 1.f / lr[mi * 2 + 1];
        int row = w0 + mi * 16 + gp;
        #pragma unroll
        for (int ni = 0; ni < 4; ni++) {
            int col = h * 32 + ni * 8 + 2 * tg;
            *(float2*)(ctx + (size_t)(b * 256 + row) * 256 + col) =
                make_float2(oacc[mi][ni][0] * inv0, oacc[mi][ni][1] * inv0);
            *(float2*)(ctx + (size_t)(b * 256 + row + 8) * 256 + col) =
                make_float2(oacc[mi][ni][2] * inv1, oacc[mi][ni][3] * inv1);
        }
    }
}

// ================= pooling =================
__global__ __launch_bounds__(256) void pool_kernel(
    const float* __restrict__ x, const float* __restrict__ pw, const float* __restrict__ pb,
    const float* __restrict__ code_mask, float* __restrict__ out)
{
    __shared__ float sp[256], sq[256];
    int b = blockIdx.x;
    int j = threadIdx.x;
    const float* xr = x + ((size_t)b * 256 + j) * 256;
    float s = 0.f;
    for (int t = 0; t < 256; t++) s += xr[t] * pw[t];
    s += pb[0] + (1.f - code_mask[b * 256 + j]) * VERY_NEG;
    sq[j] = s;
    __syncthreads();
    for (int o = 128; o; o >>= 1) { if (j < o) sq[j] = fmaxf(sq[j], sq[j + o]); __syncthreads(); }
    float mx = sq[0];
    __syncthreads();
    float e = __expf(s - mx);
    sp[j] = e; sq[j] = e;
    __syncthreads();
    for (int o = 128; o; o >>= 1) { if (j < o) sq[j] += sq[j + o]; __syncthreads(); }
    float inv = 1.f / sq[0];
    __syncthreads();
    float o = 0.f;
    for (int t = 0; t < 256; t++) o += sp[t] * x[((size_t)b * 256 + t) * 256 + j];
    out[(size_t)b * 256 + j] = o * inv;
}

// ================= launch =================
extern "C" void kernel_launch(void* const* d_in, const int* in_sizes, int n_in,
                              void* d_out, int out_size)
{
    const int*   input_ids = (const int*)  d_in[0];
    const float* code_mask = (const float*)d_in[1];
    const int*   leaves    = (const int*)  d_in[2];
    const int*   anc       = (const int*)  d_in[3];
    const float* dmask     = (const float*)d_in[4];
    const float* Einit     = (const float*)d_in[5];
    const float* Einp      = (const float*)d_in[6];
    const float* aw1       = (const float*)d_in[7];
    const float* ab1       = (const float*)d_in[8];
    const float* aw2       = (const float*)d_in[9];
    const float* ab2       = (const float*)d_in[10];
    const float* pw        = (const float*)d_in[11];
    const float* pb        = (const float*)d_in[12];
    float* out = (float*)d_out;

    float *dict, *xv, *xd, *t1, *qkv, *ctx, *ff, *scores;
    __half* wTh;
    cudaGetSymbolAddress((void**)&dict,   g_dict);
    cudaGetSymbolAddress((void**)&xv,     g_xv);
    cudaGetSymbolAddress((void**)&xd,     g_xd);
    cudaGetSymbolAddress((void**)&t1,     g_t1);
    cudaGetSymbolAddress((void**)&qkv,    g_qkv);
    cudaGetSymbolAddress((void**)&ctx,    g_ctx);
    cudaGetSymbolAddress((void**)&ff,     g_ff);
    cudaGetSymbolAddress((void**)&wTh,    g_wTh);
    cudaGetSymbolAddress((void**)&scores, g_scores);

    cudaFuncSetAttribute(f16_gemm,    cudaFuncAttributeMaxDynamicSharedMemorySize, SM_TOTAL);
    cudaFuncSetAttribute(f16_dag_mlp, cudaFuncAttributeMaxDynamicSharedMemorySize, SM_TOTAL);
    cudaFuncSetAttribute(attn_mma,    cudaFuncAttributeMaxDynamicSharedMemorySize, ATT_SMEM);

    TransArgs ta;
    ta.d[0] = {aw1, wTh + 1572864, 512, 256};
    for (int l = 0; l < 2; l++) {
        int wb = 13 + 8 * l;
        __half* base = wTh + l * 786432;
        ta.d[1 + 6 * l + 0] = {(const float*)d_in[wb + 0], base + 0,      256, 256};
        ta.d[1 + 6 * l + 1] = {(const float*)d_in[wb + 1], base + 65536,  256, 256};
        ta.d[1 + 6 * l + 2] = {(const float*)d_in[wb + 2], base + 131072, 256, 256};
        ta.d[1 + 6 * l + 3] = {(const float*)d_in[wb + 3], base + 196608, 256, 256};
        ta.d[1 + 6 * l + 4] = {(const float*)d_in[wb + 4], base + 262144, 256, 1024};
        ta.d[1 + 6 * l + 5] = {(const float*)d_in[wb + 6], base + 524288, 1024, 256};
    }
    transpose_all<<<dim3(32, 32, 13), 256>>>(ta);
    zero_scores<<<(CA_ + 255) / 256, 256>>>(scores);

    f16_dag_mlp<<<dim3(CA_ / 128, 2), 256, SM_TOTAL>>>(Einit, leaves, anc, dmask,
                                                       wTh + 1572864, ab1, aw2, scores);
    dag_reduce_kernel<<<C_ / 8, 256>>>(scores, ab2, anc, dmask, Einit, dict);
    gather_kernel<<<BS_, 256>>>(input_ids, Einp, dict, xv, xd);

    auto encoder = [&](const float* X, int l, float* O) {
        __half* base = wTh + l * 786432;
        const float* fb1 = (const float*)d_in[13 + 8 * l + 5];
        const float* fb2 = (const float*)d_in[13 + 8 * l + 7];
        f16_gemm<<<dim3(BS_ / 128, 6), 256, SM_TOTAL>>>(X, base + 0, nullptr, nullptr,
                                                        qkv, BS_, 768, 256, 0);
        attn_mma<<<B_ * 8, 256, ATT_SMEM>>>(qkv, code_mask, ctx);
        f16_gemm<<<dim3(BS_ / 128, 2), 256, SM_TOTAL>>>(ctx, base + 196608, nullptr, X,
                                                        t1, BS_, 256, 256, 0);
        f16_gemm<<<dim3(BS_ / 128, 8), 256, SM_TOTAL>>>(t1, base + 262144, fb1, nullptr,
                                                        ff, BS_, 1024, 256, 1);
        f16_gemm<<<dim3(BS_ / 128, 2), 256, SM_TOTAL>>>(ff, base + 524288, fb2, t1,
                                                        O, BS_, 256, 1024, 0);
    };
    encoder(xv, 0, out);
    encoder(xd, 1, xv);

    pool_kernel<<<B_, 256>>>(xv, pw, pb, code_mask, out + (size_t)BS_ * H_);
}

// round 16
// speedup vs baseline: 1.6168x; 1.1184x over previous
#include <cuda_runtime.h>
#include <cuda_fp16.h>
#include <cstdint>
#include <cstddef>

#define VERY_NEG -1e30f
#define B_   128
#define S_   256
#define H_   256
#define C_   20000
#define A_   8
#define BS_  (B_*S_)      // 32768
#define CA_  (C_*A_)      // 160000

// ================= scratch =================
__device__ float g_dict[(C_+1)*H_];
__device__ float g_xv[BS_*H_];
__device__ float g_xd[BS_*H_];
__device__ float g_t1[BS_*H_];
__device__ __align__(16) __half g_qkvh[BS_*768];
__device__ __align__(16) __half g_ctxh[BS_*H_];
__device__ __align__(16) __half g_ffh[BS_*4*H_];
__device__ __align__(16) __half g_wTh[1703936 + 256];
__device__ float g_scores[CA_];

// ================= PTX helpers =================
__device__ __forceinline__ uint32_t smem_u32(const void* p) {
    uint32_t a;
    asm("{ .reg .u64 t; cvta.to.shared.u64 t, %1; cvt.u32.u64 %0, t; }" : "=r"(a) : "l"(p));
    return a;
}
__device__ __forceinline__ void mma_f16(float* d, const uint32_t* a, const uint32_t* b)
{
    asm volatile(
        "mma.sync.aligned.m16n8k16.row.col.f32.f16.f16.f32 "
        "{%0,%1,%2,%3}, {%4,%5,%6,%7}, {%8,%9}, {%0,%1,%2,%3};\n"
        : "+f"(d[0]), "+f"(d[1]), "+f"(d[2]), "+f"(d[3])
        : "r"(a[0]), "r"(a[1]), "r"(a[2]), "r"(a[3]), "r"(b[0]), "r"(b[1]));
}
__device__ __forceinline__ void ldsm_x4(uint32_t* r, uint32_t addr)
{
    asm volatile("ldmatrix.sync.aligned.m8n8.x4.shared.b16 {%0,%1,%2,%3}, [%4];"
        : "=r"(r[0]), "=r"(r[1]), "=r"(r[2]), "=r"(r[3]) : "r"(addr));
}
__device__ __forceinline__ void ldsm_x2(uint32_t* r, uint32_t addr)
{
    asm volatile("ldmatrix.sync.aligned.m8n8.x2.shared.b16 {%0,%1}, [%2];"
        : "=r"(r[0]), "=r"(r[1]) : "r"(addr));
}
__device__ __forceinline__ void cp16(uint32_t saddr, const void* gptr)
{
    asm volatile("cp.async.cg.shared.global [%0], [%1], 16;" :: "r"(saddr), "l"(gptr));
}
#define CP_COMMIT() asm volatile("cp.async.commit_group;" ::: "memory")
#define CP_WAIT(n)  asm volatile("cp.async.wait_group %0;" :: "n"(n) : "memory")
__device__ __forceinline__ uint2 pack4h(float4 f)
{
    __half2 a = __floats2half2_rn(f.x, f.y);
    __half2 b = __floats2half2_rn(f.z, f.w);
    uint2 r;
    r.x = *(uint32_t*)&a;
    r.y = *(uint32_t*)&b;
    return r;
}

// ---- fp16 GEMM smem geometry: BK=64 halves, stride 72 halves ----
#define SH       72
#define SMT      (128 * SH * 2)
#define SM_TOTAL (4 * SMT)

// one 128x128x64 block-step via LDSM fp16 fragment loads
__device__ __forceinline__ void mma_block_f16(uint32_t sA, uint32_t sB,
                                              int wm, int wn, int lane, float acc[4][4][4])
{
    uint32_t aoff = sA + (uint32_t)(((wm * 64 + (lane & 15)) * SH + (lane >> 4) * 8) * 2);
    uint32_t boff = sB + (uint32_t)(((wn * 32 + (lane & 7)) * SH + ((lane >> 3) & 1) * 8) * 2);
    #pragma unroll
    for (int ks = 0; ks < 4; ks++) {
        uint32_t a[4][4], b[4][2];
        #pragma unroll
        for (int mi = 0; mi < 4; mi++)
            ldsm_x4(a[mi], aoff + (uint32_t)((mi * 16 * SH + ks * 16) * 2));
        #pragma unroll
        for (int ni = 0; ni < 4; ni++)
            ldsm_x2(b[ni], boff + (uint32_t)((ni * 8 * SH + ks * 16) * 2));
        #pragma unroll
        for (int mi = 0; mi < 4; mi++)
            #pragma unroll
            for (int ni = 0; ni < 4; ni++)
                mma_f16(acc[mi][ni], a[mi], b[ni]);
    }
}

// ================= templated fp16 GEMM =================
// AH: A operand is fp16 (cp.async staged); else fp32 (reg-staged + pack).
// OH: output fp16; else fp32 (+bias/res/relu options).
template<bool AH, bool OH>
__global__ __launch_bounds__(256) void f16_gemm_t(
    const void* __restrict__ Ap, const __half* __restrict__ Bth,
    const float* __restrict__ bias, const float* __restrict__ res,
    void* __restrict__ Cp, int M, int N, int K, int do_relu)
{
    extern __shared__ char smc[];
    uint32_t smb = smem_u32(smc);
    int tid = threadIdx.x;
    int bm = blockIdx.x, bn = blockIdx.y;
    int lane = tid & 31, wid = tid >> 5;
    int wm = wid >> 2, wn = wid & 3;
    int r0 = tid >> 3, c4 = tid & 7;

    const float*  Af = (const float*)Ap;
    const __half* Ah = (const __half*)Ap;
    const float*  Abf = Af + (size_t)(bm * 128 + r0) * K + c4 * 4;
    const __half* Abh = Ah + (size_t)(bm * 128 + r0) * K + c4 * 8;
    const __half* Bb  = Bth + (size_t)(bn * 128 + r0) * K + c4 * 8;
    uint32_t sAoff = AH ? (uint32_t)((r0 * SH + c4 * 8) * 2) : (uint32_t)((r0 * SH + c4 * 4) * 2);
    uint32_t sBoff = (uint32_t)((r0 * SH + c4 * 8) * 2);

    float acc[4][4][4];
    #pragma unroll
    for (int i = 0; i < 4; i++)
        #pragma unroll
        for (int j = 0; j < 4; j++)
            #pragma unroll
            for (int t = 0; t < 4; t++) acc[i][j][t] = 0.f;

    int NC = K >> 6;
    float4 fa[4][2];
    // prologue
    #pragma unroll
    for (int i = 0; i < 4; i++)
        cp16(smb + (uint32_t)SMT + sBoff + (uint32_t)(i * 32 * SH * 2), Bb + (size_t)i * 32 * K);
    if (AH) {
        #pragma unroll
        for (int i = 0; i < 4; i++)
            cp16(smb + sAoff + (uint32_t)(i * 32 * SH * 2), Abh + (size_t)i * 32 * K);
    }
    CP_COMMIT();
    if (!AH) {
        #pragma unroll
        for (int i = 0; i < 4; i++) {
            fa[i][0] = *(const float4*)(Abf + (size_t)i * 32 * K);
            fa[i][1] = *(const float4*)(Abf + (size_t)i * 32 * K + 32);
        }
        #pragma unroll
        for (int i = 0; i < 4; i++) {
            *(uint2*)(smc + sAoff + (uint32_t)(i * 32 * SH * 2))        = pack4h(fa[i][0]);
            *(uint2*)(smc + sAoff + (uint32_t)((i * 32 * SH + 32) * 2)) = pack4h(fa[i][1]);
        }
    }
    CP_WAIT(0);
    __syncthreads();

    for (int kc = 0; kc < NC; kc++) {
        int buf = kc & 1;
        int nb = buf ^ 1;
        if (kc + 1 < NC) {
            int k0 = (kc + 1) << 6;
            #pragma unroll
            for (int i = 0; i < 4; i++)
                cp16(smb + (uint32_t)(nb * 2 * SMT + SMT) + sBoff + (uint32_t)(i * 32 * SH * 2),
                     Bb + (size_t)i * 32 * K + k0);
            if (AH) {
                #pragma unroll
                for (int i = 0; i < 4; i++)
                    cp16(smb + (uint32_t)(nb * 2 * SMT) + sAoff + (uint32_t)(i * 32 * SH * 2),
                         Abh + (size_t)i * 32 * K + k0);
            }
            CP_COMMIT();
            if (!AH) {
                #pragma unroll
                for (int i = 0; i < 4; i++) {
                    fa[i][0] = *(const float4*)(Abf + (size_t)i * 32 * K + k0);
                    fa[i][1] = *(const float4*)(Abf + (size_t)i * 32 * K + k0 + 32);
                }
            }
        }
        mma_block_f16(smb + (uint32_t)(buf * 2 * SMT),
                      smb + (uint32_t)(buf * 2 * SMT + SMT), wm, wn, lane, acc);
        if (kc + 1 < NC) {
            if (!AH) {
                #pragma unroll
                for (int i = 0; i < 4; i++) {
                    *(uint2*)(smc + (uint32_t)(nb * 2 * SMT) + sAoff + (uint32_t)(i * 32 * SH * 2))
                        = pack4h(fa[i][0]);
                    *(uint2*)(smc + (uint32_t)(nb * 2 * SMT) + sAoff + (uint32_t)((i * 32 * SH + 32) * 2))
                        = pack4h(fa[i][1]);
                }
            }
            CP_WAIT(0);
            __syncthreads();
        }
    }

    int tg = lane & 3, gp = lane >> 2;
    #pragma unroll
    for (int mi = 0; mi < 4; mi++) {
        #pragma unroll
        for (int ni = 0; ni < 4; ni++) {
            int rl = wm * 64 + mi * 16 + gp;
            int col = bn * 128 + wn * 32 + ni * 8 + tg * 2;
            float2 bv = make_float2(0.f, 0.f);
            if (bias) bv = *(const float2*)(bias + col);
            #pragma unroll
            for (int h = 0; h < 2; h++) {
                size_t rowg = (size_t)bm * 128 + rl + h * 8;
                float2 v = make_float2(acc[mi][ni][2 * h] + bv.x, acc[mi][ni][2 * h + 1] + bv.y);
                if (res) {
                    float2 rv = *(const float2*)(res + rowg * N + col);
                    v.x += rv.x; v.y += rv.y;
                }
                if (do_relu) { v.x = fmaxf(v.x, 0.f); v.y = fmaxf(v.y, 0.f); }
                if (OH)
                    *(__half2*)((__half*)Cp + rowg * N + col) = __floats2half2_rn(v.x, v.y);
                else
                    *(float2*)((float*)Cp + rowg * N + col) = v;
            }
        }
    }
}

// ================= DAG MLP fused (fp16) =================
__global__ __launch_bounds__(256) void f16_dag_mlp(
    const float* __restrict__ E, const int* __restrict__ leaves, const int* __restrict__ anc,
    const float* __restrict__ dmask, const __half* __restrict__ w1Th,
    const float* __restrict__ b1, const float* __restrict__ w2, float* __restrict__ scores)
{
    extern __shared__ char smc[];
    uint32_t smb = smem_u32(smc);
    int tid = threadIdx.x;
    int bm = blockIdx.x, bn = blockIdx.y;
    int lane = tid & 31, wid = tid >> 5;
    int wm = wid >> 2, wn = wid & 3;
    int r0 = tid >> 3, c4 = tid & 7;

    int nl[4], na[4];
    #pragma unroll
    for (int i = 0; i < 4; i++) {
        int m = bm * 128 + r0 + i * 32;
        nl[i] = leaves[m]; na[i] = anc[m];
    }
    const __half* Bb = w1Th + (size_t)(bn * 128 + r0) * 512 + c4 * 8;
    uint32_t sAoff = (uint32_t)((r0 * SH + c4 * 4) * 2);
    uint32_t sBoff = (uint32_t)((r0 * SH + c4 * 8) * 2);

    float acc[4][4][4];
    #pragma unroll
    for (int i = 0; i < 4; i++)
        #pragma unroll
        for (int j = 0; j < 4; j++)
            #pragma unroll
            for (int t = 0; t < 4; t++) acc[i][j][t] = 0.f;

    const int NC = 8;
    float4 fa[4][2];
    #pragma unroll
    for (int i = 0; i < 4; i++)
        cp16(smb + (uint32_t)SMT + sBoff + (uint32_t)(i * 32 * SH * 2), Bb + (size_t)i * 32 * 512);
    CP_COMMIT();
    #pragma unroll
    for (int i = 0; i < 4; i++) {
        const float* src = E + (size_t)nl[i] * 256 + c4 * 4;
        fa[i][0] = *(const float4*)(src);
        fa[i][1] = *(const float4*)(src + 32);
    }
    #pragma unroll
    for (int i = 0; i < 4; i++) {
        *(uint2*)(smc + sAoff + (uint32_t)(i * 32 * SH * 2))        = pack4h(fa[i][0]);
        *(uint2*)(smc + sAoff + (uint32_t)((i * 32 * SH + 32) * 2)) = pack4h(fa[i][1]);
    }
    CP_WAIT(0);
    __syncthreads();

    for (int kc = 0; kc < NC; kc++) {
        int buf = kc & 1;
        int nb = buf ^ 1;
        if (kc + 1 < NC) {
            int k0 = (kc + 1) << 6;
            int kk = k0 & 255;
            bool first = k0 < 256;
            #pragma unroll
            for (int i = 0; i < 4; i++)
                cp16(smb + (uint32_t)(nb * 2 * SMT + SMT) + sBoff + (uint32_t)(i * 32 * SH * 2),
                     Bb + (size_t)i * 32 * 512 + k0);
            CP_COMMIT();
            #pragma unroll
            for (int i = 0; i < 4; i++) {
                int node = first ? nl[i] : na[i];
                const float* src = E + (size_t)node * 256 + kk + c4 * 4;
                fa[i][0] = *(const float4*)(src);
                fa[i][1] = *(const float4*)(src + 32);
            }
        }
        mma_block_f16(smb + (uint32_t)(buf * 2 * SMT),
                      smb + (uint32_t)(buf * 2 * SMT + SMT), wm, wn, lane, acc);
        if (kc + 1 < NC) {
            #pragma unroll
            for (int i = 0; i < 4; i++) {
                *(uint2*)(smc + (uint32_t)(nb * 2 * SMT) + sAoff + (uint32_t)(i * 32 * SH * 2))
                    = pack4h(fa[i][0]);
                *(uint2*)(smc + (uint32_t)(nb * 2 * SMT) + sAoff + (uint32_t)((i * 32 * SH + 32) * 2))
                    = pack4h(fa[i][1]);
            }
            CP_WAIT(0);
            __syncthreads();
        }
    }

    int tg = lane & 3, gp = lane >> 2;
    float2 bv[4], w2v[4];
    #pragma unroll
    for (int ni = 0; ni < 4; ni++) {
        int col = bn * 128 + wn * 32 + ni * 8 + tg * 2;
        bv[ni] = *(const float2*)(b1 + col);
        w2v[ni] = *(const float2*)(w2 + col);
    }
    #pragma unroll
    for (int mi = 0; mi < 4; mi++) {
        int rl = wm * 64 + mi * 16 + gp;
        float mk0 = dmask[bm * 128 + rl];
        float mk1 = dmask[bm * 128 + rl + 8];
        float p0 = 0.f, p1 = 0.f;
        #pragma unroll
        for (int ni = 0; ni < 4; ni++) {
            float v0x = fmaxf(mk0 * acc[mi][ni][0] + bv[ni].x, 0.f);
            float v0y = fmaxf(mk0 * acc[mi][ni][1] + bv[ni].y, 0.f);
            float v1x = fmaxf(mk1 * acc[mi][ni][2] + bv[ni].x, 0.f);
            float v1y = fmaxf(mk1 * acc[mi][ni][3] + bv[ni].y, 0.f);
            p0 += v0x * w2v[ni].x + v0y * w2v[ni].y;
            p1 += v1x * w2v[ni].x + v1y * w2v[ni].y;
        }
        p0 += __shfl_xor_sync(0xffffffffu, p0, 1);
        p0 += __shfl_xor_sync(0xffffffffu, p0, 2);
        p1 += __shfl_xor_sync(0xffffffffu, p1, 1);
        p1 += __shfl_xor_sync(0xffffffffu, p1, 2);
        if (tg == 0) {
            atomicAdd(scores + bm * 128 + rl, p0);
            atomicAdd(scores + bm * 128 + rl + 8, p1);
        }
    }
}

// ================= zero scores =================
__global__ __launch_bounds__(256) void zero_scores(float* s)
{
    int i = blockIdx.x * 256 + threadIdx.x;
    if (i < CA_) s[i] = 0.f;
}

// ================= batched transpose -> fp16 =================
struct TransDesc { const float* src; __half* dst; int R, C; };
struct TransArgs { TransDesc d[13]; };
__global__ __launch_bounds__(256) void transpose_all(TransArgs args)
{
    TransDesc t = args.d[blockIdx.z];
    if (blockIdx.x * 32 >= t.C || blockIdx.y * 32 >= t.R) return;
    __shared__ float tt[32][33];
    int x = threadIdx.x & 31, y0 = threadIdx.x >> 5;
    int c = blockIdx.x * 32 + x;
    #pragma unroll
    for (int i = 0; i < 32; i += 8)
        tt[y0 + i][x] = t.src[(size_t)(blockIdx.y * 32 + y0 + i) * t.C + c];
    __syncthreads();
    int rr = blockIdx.y * 32 + x;
    #pragma unroll
    for (int i = 0; i < 32; i += 8)
        t.dst[(size_t)(blockIdx.x * 32 + y0 + i) * t.R + rr] = __float2half_rn(tt[x][y0 + i]);
}

// ================= DAG reduce =================
__global__ __launch_bounds__(256) void dag_reduce_kernel(
    const float* __restrict__ scores, const float* __restrict__ b2,
    const int* __restrict__ anc, const float* __restrict__ dmask,
    const float* __restrict__ E, float* __restrict__ dict)
{
    int warp = threadIdx.x >> 5, lane = threadIdx.x & 31;
    if (blockIdx.x == 0) dict[threadIdx.x] = 0.f;
    int c = blockIdx.x * 8 + warp;
    if (c >= C_) return;
    float p[8];
    float esum = 0.f;
    float b2v = b2[0];
    #pragma unroll
    for (int a = 0; a < 8; a++) {
        float mkk = dmask[c * 8 + a];
        float s = scores[c * 8 + a] + b2v + (1.f - mkk) * VERY_NEG;
        float e = __expf(s);
        esum += e;
        p[a] = e * mkk;
    }
    float inv = 1.f / esum;
    int nodes[8];
    #pragma unroll
    for (int a = 0; a < 8; a++) nodes[a] = anc[c * 8 + a];
    for (int t = lane; t < 256; t += 32) {
        float o = 0.f;
        #pragma unroll
        for (int a = 0; a < 8; a++) o += p[a] * E[(size_t)nodes[a] * 256 + t];
        dict[(size_t)(c + 1) * 256 + t] = o * inv;
    }
}

// ================= gather =================
__global__ __launch_bounds__(256) void gather_kernel(
    const int* __restrict__ ids, const float* __restrict__ Ein,
    const float* __restrict__ dict, float* __restrict__ xv, float* __restrict__ xd)
{
    int bs = blockIdx.x;
    int t = threadIdx.x;
    int id = ids[bs];
    size_t o = (size_t)bs * 256 + t;
    xv[o] = Ein[(size_t)id * 256 + t];
    xd[o] = dict[(size_t)id * 256 + t];
}

// ================= fp16 tensor-core attention =================
// smem halves: Ks[256][40], Vt[32][264], Ps[256][40], Ms[256] fp32
#define KS_OFF  0
#define VT_OFF  20480
#define PS_OFF  37376
#define MS_OFF  57856
#define ATT_SMEM 58880
__global__ __launch_bounds__(256, 2) void attn_mma_f16(
    const __half* __restrict__ qkv, const float* __restrict__ code_mask, __half* __restrict__ ctx)
{
    extern __shared__ char smc[];
    uint32_t smb = smem_u32(smc);
    float* Ms = (float*)(smc + MS_OFF);
    int bh = blockIdx.x;
    int b = bh >> 3, h = bh & 7;
    int tid = threadIdx.x, lane = tid & 31, wid = tid >> 5;
    int tg = lane & 3, gp = lane >> 2;
    int w0 = wid * 32;
    const size_t qb = (size_t)b * 256 * 768 + h * 32;

    // staging: thread j handles row j
    {
        int j = tid;
        const __half* qrow = qkv + qb + (size_t)j * 768;
        #pragma unroll
        for (int t = 0; t < 4; t++) {
            *(uint4*)(smc + PS_OFF + j * 80 + t * 16) = *(const uint4*)(qrow + t * 8);
            *(uint4*)(smc + KS_OFF + j * 80 + t * 16) = *(const uint4*)(qrow + 256 + t * 8);
        }
        union { uint4 u; __half hh[8]; } vv;
        #pragma unroll
        for (int t = 0; t < 4; t++) {
            vv.u = *(const uint4*)(qrow + 512 + t * 8);
            #pragma unroll
            for (int e = 0; e < 8; e++) {
                int d = t * 8 + e;
                *(__half*)(smc + VT_OFF + (d * 264 + j) * 2) = vv.hh[e];
            }
        }
        Ms[tid] = (1.f - code_mask[b * 256 + tid]) * VERY_NEG;
    }
    __syncthreads();

    uint32_t aoffQ = smb + (uint32_t)PS_OFF + (uint32_t)(((lane & 15) * 40 + (lane >> 4) * 8) * 2);
    uint32_t boffK = smb + (uint32_t)KS_OFF + (uint32_t)(((lane & 7) * 40 + ((lane >> 3) & 1) * 8) * 2);
    uint32_t boffV = smb + (uint32_t)VT_OFF + (uint32_t)(((lane & 7) * 264 + ((lane >> 3) & 1) * 8) * 2);

    // Q fragments (rows w0..w0+31), hoisted before Ps is overwritten by P
    uint32_t qa[2][2][4];
    #pragma unroll
    for (int mi = 0; mi < 2; mi++)
        #pragma unroll
        for (int ks = 0; ks < 2; ks++)
            ldsm_x4(qa[mi][ks], aoffQ + (uint32_t)((((w0 + mi * 16) * 40) + ks * 16) * 2));

    float oacc[2][4][4];
    #pragma unroll
    for (int i = 0; i < 2; i++)
        #pragma unroll
        for (int j = 0; j < 4; j++)
            #pragma unroll
            for (int t = 0; t < 4; t++) oacc[i][j][t] = 0.f;
    float lr[4] = {0.f, 0.f, 0.f, 0.f};
    const float scale = 0.17677669529663687f;

    for (int jc = 0; jc < 8; jc++) {
        int j0 = jc * 32;
        float sacc[2][4][4];
        #pragma unroll
        for (int i = 0; i < 2; i++)
            #pragma unroll
            for (int j = 0; j < 4; j++)
                #pragma unroll
                for (int t = 0; t < 4; t++) sacc[i][j][t] = 0.f;
        #pragma unroll
        for (int ks = 0; ks < 2; ks++) {
            uint32_t bfr[4][2];
            #pragma unroll
            for (int ni = 0; ni < 4; ni++)
                ldsm_x2(bfr[ni], boffK + (uint32_t)((((j0 + ni * 8) * 40) + ks * 16) * 2));
            #pragma unroll
            for (int mi = 0; mi < 2; mi++)
                #pragma unroll
                for (int ni = 0; ni < 4; ni++)
                    mma_f16(sacc[mi][ni], qa[mi][ks], bfr[ni]);
        }
        __syncwarp();
        #pragma unroll
        for (int mi = 0; mi < 2; mi++) {
            int row = w0 + mi * 16 + gp;
            #pragma unroll
            for (int ni = 0; ni < 4; ni++) {
                int colg = j0 + ni * 8 + 2 * tg;
                float m0 = Ms[colg], m1 = Ms[colg + 1];
                float e0 = __expf(sacc[mi][ni][0] * scale + m0);
                float e1 = __expf(sacc[mi][ni][1] * scale + m1);
                float e2 = __expf(sacc[mi][ni][2] * scale + m0);
                float e3 = __expf(sacc[mi][ni][3] * scale + m1);
                lr[mi * 2 + 0] += e0 + e1;
                lr[mi * 2 + 1] += e2 + e3;
                int cl = ni * 8 + 2 * tg;
                *(__half2*)(smc + PS_OFF + (row * 40 + cl) * 2)       = __floats2half2_rn(e0, e1);
                *(__half2*)(smc + PS_OFF + ((row + 8) * 40 + cl) * 2) = __floats2half2_rn(e2, e3);
            }
        }
        __syncwarp();
        #pragma unroll
        for (int ks2 = 0; ks2 < 2; ks2++) {
            uint32_t pa[2][4], bvv[4][2];
            #pragma unroll
            for (int mi = 0; mi < 2; mi++)
                ldsm_x4(pa[mi], aoffQ + (uint32_t)((((w0 + mi * 16) * 40) + ks2 * 16) * 2));
            #pragma unroll
            for (int ni = 0; ni < 4; ni++)
                ldsm_x2(bvv[ni], boffV + (uint32_t)((((ni * 8) * 264) + j0 + ks2 * 16) * 2));
            #pragma unroll
            for (int mi = 0; mi < 2; mi++)
                #pragma unroll
                for (int ni = 0; ni < 4; ni++)
                    mma_f16(oacc[mi][ni], pa[mi], bvv[ni]);
        }
        __syncwarp();
    }

    #pragma unroll
    for (int i = 0; i < 4; i++) {
        lr[i] += __shfl_xor_sync(0xffffffffu, lr[i], 1);
        lr[i] += __shfl_xor_sync(0xffffffffu, lr[i], 2);
    }
    #pragma unroll
    for (int mi = 0; mi < 2; mi++) {
        float inv0 = 1.f / lr[mi * 2 + 0];
        float inv1 = 1.f / lr[mi * 2 + 1];
        int row = w0 + mi * 16 + gp;
        #pragma unroll
        for (int ni = 0; ni < 4; ni++) {
            int col = h * 32 + ni * 8 + 2 * tg;
            *(__half2*)(ctx + (size_t)(b * 256 + row) * 256 + col) =
                __floats2half2_rn(oacc[mi][ni][0] * inv0, oacc[mi][ni][1] * inv0);
            *(__half2*)(ctx + (size_t)(b * 256 + row + 8) * 256 + col) =
                __floats2half2_rn(oacc[mi][ni][2] * inv1, oacc[mi][ni][3] * inv1);
        }
    }
}

// ================= pooling =================
__global__ __launch_bounds__(256) void pool_kernel(
    const float* __restrict__ x, const float* __restrict__ pw, const float* __restrict__ pb,
    const float* __restrict__ code_mask, float* __restrict__ out)
{
    __shared__ float sp[256], sq[256];
    int b = blockIdx.x;
    int j = threadIdx.x;
    const float* xr = x + ((size_t)b * 256 + j) * 256;
    float s = 0.f;
    for (int t = 0; t < 256; t++) s += xr[t] * pw[t];
    s += pb[0] + (1.f - code_mask[b * 256 + j]) * VERY_NEG;
    sq[j] = s;
    __syncthreads();
    for (int o = 128; o; o >>= 1) { if (j < o) sq[j] = fmaxf(sq[j], sq[j + o]); __syncthreads(); }
    float mx = sq[0];
    __syncthreads();
    float e = __expf(s - mx);
    sp[j] = e; sq[j] = e;
    __syncthreads();
    for (int o = 128; o; o >>= 1) { if (j < o) sq[j] += sq[j + o]; __syncthreads(); }
    float inv = 1.f / sq[0];
    __syncthreads();
    float o = 0.f;
    for (int t = 0; t < 256; t++) o += sp[t] * x[((size_t)b * 256 + t) * 256 + j];
    out[(size_t)b * 256 + j] = o * inv;
}

// ================= launch =================
extern "C" void kernel_launch(void* const* d_in, const int* in_sizes, int n_in,
                              void* d_out, int out_size)
{
    const int*   input_ids = (const int*)  d_in[0];
    const float* code_mask = (const float*)d_in[1];
    const int*   leaves    = (const int*)  d_in[2];
    const int*   anc       = (const int*)  d_in[3];
    const float* dmask     = (const float*)d_in[4];
    const float* Einit     = (const float*)d_in[5];
    const float* Einp      = (const float*)d_in[6];
    const float* aw1       = (const float*)d_in[7];
    const float* ab1       = (const float*)d_in[8];
    const float* aw2       = (const float*)d_in[9];
    const float* ab2       = (const float*)d_in[10];
    const float* pw        = (const float*)d_in[11];
    const float* pb        = (const float*)d_in[12];
    float* out = (float*)d_out;

    float *dict, *xv, *xd, *t1, *scores;
    __half *wTh, *qkvh, *ctxh, *ffh;
    cudaGetSymbolAddress((void**)&dict,   g_dict);
    cudaGetSymbolAddress((void**)&xv,     g_xv);
    cudaGetSymbolAddress((void**)&xd,     g_xd);
    cudaGetSymbolAddress((void**)&t1,     g_t1);
    cudaGetSymbolAddress((void**)&qkvh,   g_qkvh);
    cudaGetSymbolAddress((void**)&ctxh,   g_ctxh);
    cudaGetSymbolAddress((void**)&ffh,    g_ffh);
    cudaGetSymbolAddress((void**)&wTh,    g_wTh);
    cudaGetSymbolAddress((void**)&scores, g_scores);

    cudaFuncSetAttribute(f16_gemm_t<false, true>,  cudaFuncAttributeMaxDynamicSharedMemorySize, SM_TOTAL);
    cudaFuncSetAttribute(f16_gemm_t<false, false>, cudaFuncAttributeMaxDynamicSharedMemorySize, SM_TOTAL);
    cudaFuncSetAttribute(f16_gemm_t<true, false>,  cudaFuncAttributeMaxDynamicSharedMemorySize, SM_TOTAL);
    cudaFuncSetAttribute(f16_dag_mlp,  cudaFuncAttributeMaxDynamicSharedMemorySize, SM_TOTAL);
    cudaFuncSetAttribute(attn_mma_f16, cudaFuncAttributeMaxDynamicSharedMemorySize, ATT_SMEM);

    TransArgs ta;
    ta.d[0] = {aw1, wTh + 1572864, 512, 256};
    for (int l = 0; l < 2; l++) {
        int wb = 13 + 8 * l;
        __half* base = wTh + l * 786432;
        ta.d[1 + 6 * l + 0] = {(const float*)d_in[wb + 0], base + 0,      256, 256};
        ta.d[1 + 6 * l + 1] = {(const float*)d_in[wb + 1], base + 65536,  256, 256};
        ta.d[1 + 6 * l + 2] = {(const float*)d_in[wb + 2], base + 131072, 256, 256};
        ta.d[1 + 6 * l + 3] = {(const float*)d_in[wb + 3], base + 196608, 256, 256};
        ta.d[1 + 6 * l + 4] = {(const float*)d_in[wb + 4], base + 262144, 256, 1024};
        ta.d[1 + 6 * l + 5] = {(const float*)d_in[wb + 6], base + 524288, 1024, 256};
    }
    transpose_all<<<dim3(32, 32, 13), 256>>>(ta);
    zero_scores<<<(CA_ + 255) / 256, 256>>>(scores);

    f16_dag_mlp<<<dim3(CA_ / 128, 2), 256, SM_TOTAL>>>(Einit, leaves, anc, dmask,
                                                       wTh + 1572864, ab1, aw2, scores);
    dag_reduce_kernel<<<C_ / 8, 256>>>(scores, ab2, anc, dmask, Einit, dict);
    gather_kernel<<<BS_, 256>>>(input_ids, Einp, dict, xv, xd);

    auto encoder = [&](const float* X, int l, float* O) {
        __half* base = wTh + l * 786432;
        const float* fb1 = (const float*)d_in[13 + 8 * l + 5];
        const float* fb2 = (const float*)d_in[13 + 8 * l + 7];
        // qkv: fp32 A, fp16 out
        f16_gemm_t<false, true><<<dim3(BS_ / 128, 6), 256, SM_TOTAL>>>(
            X, base + 0, nullptr, nullptr, qkvh, BS_, 768, 256, 0);
        attn_mma_f16<<<B_ * 8, 256, ATT_SMEM>>>(qkvh, code_mask, ctxh);
        // wo: fp16 A (ctx), fp32 out with residual X
        f16_gemm_t<true, false><<<dim3(BS_ / 128, 2), 256, SM_TOTAL>>>(
            ctxh, base + 196608, nullptr, X, t1, BS_, 256, 256, 0);
        // FFN1: fp32 A (t1), fp16 out with bias+relu
        f16_gemm_t<false, true><<<dim3(BS_ / 128, 8), 256, SM_TOTAL>>>(
            t1, base + 262144, fb1, nullptr, ffh, BS_, 1024, 256, 1);
        // FFN2: fp16 A (ff), fp32 out with bias + residual t1
        f16_gemm_t<true, false><<<dim3(BS_ / 128, 2), 256, SM_TOTAL>>>(
            ffh, base + 524288, fb2, t1, O, BS_, 256, 1024, 0);
    };
    encoder(xv, 0, out);
    encoder(xd, 1, xv);

    pool_kernel<<<B_, 256>>>(xv, pw, pb, code_mask, out + (size_t)BS_ * H_);
}